// round 6
// baseline (speedup 1.0000x reference)
#include <cuda_runtime.h>
#include <cuda_bf16.h>
#include <math.h>

#define BDIM  2
#define TSEQ  2048
#define CDIM  2048
#define NHEAD 16
#define HD    128

// ---------------- split bf16 hi/lo scratch (device globals) ----------------
__device__ unsigned g_xh [(size_t)BDIM * TSEQ * CDIM / 2];
__device__ unsigned g_xl [(size_t)BDIM * TSEQ * CDIM / 2];
__device__ unsigned g_wah[(size_t)CDIM * 3 * CDIM / 2];
__device__ unsigned g_wal[(size_t)CDIM * 3 * CDIM / 2];
__device__ unsigned g_wph[(size_t)CDIM * CDIM / 2];
__device__ unsigned g_wpl[(size_t)CDIM * CDIM / 2];
__device__ unsigned g_qkvh[(size_t)BDIM * TSEQ * 3 * CDIM / 2];
__device__ unsigned g_qkvl[(size_t)BDIM * TSEQ * 3 * CDIM / 2];
__device__ unsigned g_atth[(size_t)BDIM * TSEQ * CDIM / 2];
__device__ unsigned g_attl[(size_t)BDIM * TSEQ * CDIM / 2];

// ---------------- helpers ----------------
__device__ __forceinline__ unsigned smem_u32(const void* p) {
    unsigned a;
    asm("{ .reg .u64 t; cvta.to.shared.u64 t, %1; cvt.u32.u64 %0, t; }"
        : "=r"(a) : "l"(p));
    return a;
}

// Split two fp32 into packed bf16 hi-pair and lo-pair (residual).
__device__ __forceinline__ void split2(float x, float y, unsigned& hi, unsigned& lo) {
    unsigned h;
    asm("cvt.rn.bf16x2.f32 %0, %1, %2;" : "=r"(h) : "f"(y), "f"(x));
    float hx = __uint_as_float(h << 16);
    float hy = __uint_as_float(h & 0xffff0000u);
    float rx = x - hx;
    float ry = y - hy;
    unsigned l;
    asm("cvt.rn.bf16x2.f32 %0, %1, %2;" : "=r"(l) : "f"(ry), "f"(rx));
    hi = h; lo = l;
}

__device__ __forceinline__ void mma16816(float* d, const unsigned* a, const unsigned* b) {
    asm("mma.sync.aligned.m16n8k16.row.col.f32.bf16.bf16.f32 "
        "{%0,%1,%2,%3}, {%4,%5,%6,%7}, {%8,%9}, {%0,%1,%2,%3};"
        : "+f"(d[0]), "+f"(d[1]), "+f"(d[2]), "+f"(d[3])
        : "r"(a[0]), "r"(a[1]), "r"(a[2]), "r"(a[3]), "r"(b[0]), "r"(b[1]));
}

__device__ __forceinline__ void ldsm_x4(unsigned* r, unsigned addr) {
    asm volatile("ldmatrix.sync.aligned.m8n8.x4.shared.b16 {%0,%1,%2,%3}, [%4];"
                 : "=r"(r[0]), "=r"(r[1]), "=r"(r[2]), "=r"(r[3]) : "r"(addr));
}
__device__ __forceinline__ void ldsm_x2(unsigned* r, unsigned addr) {
    asm volatile("ldmatrix.sync.aligned.m8n8.x2.shared.b16 {%0,%1}, [%2];"
                 : "=r"(r[0]), "=r"(r[1]) : "r"(addr));
}
__device__ __forceinline__ void ldsm_x2t(unsigned* r, unsigned addr) {
    asm volatile("ldmatrix.sync.aligned.m8n8.x2.trans.shared.b16 {%0,%1}, [%2];"
                 : "=r"(r[0]), "=r"(r[1]) : "r"(addr));
}

__device__ __forceinline__ void cp16(unsigned dst, const void* src) {
    asm volatile("cp.async.cg.shared.global [%0], [%1], 16;" :: "r"(dst), "l"(src) : "memory");
}
__device__ __forceinline__ void cp_commit() {
    asm volatile("cp.async.commit_group;" ::: "memory");
}
template<int N> __device__ __forceinline__ void cp_wait() {
    asm volatile("cp.async.wait_group %0;" :: "n"(N) : "memory");
}

// ---------------------------------------------------------------------------
// fp32 -> bf16 hi/lo split preprocessing
// ---------------------------------------------------------------------------
__global__ void split_kernel(const float2* __restrict__ in,
                             unsigned* __restrict__ hi, unsigned* __restrict__ lo, int n2)
{
    int i = blockIdx.x * blockDim.x + threadIdx.x;
    if (i < n2) {
        float2 v = in[i];
        unsigned h, l;
        split2(v.x, v.y, h, l);
        hi[i] = h; lo[i] = l;
    }
}

// ---------------------------------------------------------------------------
// bf16-in GEMM + bias, 3-term split accumulate. cp.async 2-stage pipeline.
// Block 128x128, BK=32, 256 threads (8 warps, warp tile 64x32).
// SPLIT_OUT: write hi/lo bf16 packed pairs; else fp32.
// ---------------------------------------------------------------------------
#define GBM 128
#define GBN 128
#define GBK 32
#define ASTRIDE 40      // bf16 units per A row (80 B)
#define BSTRIDE 136     // bf16 units per B row (272 B)

// uint offsets in dynamic smem (per array; 2 stages each)
#define G_AH(s) ((s) * 2560)
#define G_AL(s) (5120 + (s) * 2560)
#define G_BH(s) (10240 + (s) * 2176)
#define G_BL(s) (14592 + (s) * 2176)
#define GEMM_SMEM (18944 * 4)   // 75776 bytes

template<bool SPLIT_OUT>
__global__ void __launch_bounds__(256, 1) gemm_bf16_kernel(
    const char* __restrict__ Ah, const char* __restrict__ Al,
    const char* __restrict__ Bh, const char* __restrict__ Bl,
    const float* __restrict__ bias,
    float* __restrict__ Cf, unsigned* __restrict__ Chi, unsigned* __restrict__ Clo,
    int M, int N, int K)
{
    extern __shared__ unsigned gsm[];
    const unsigned base = smem_u32(gsm);

    const int tid  = threadIdx.x;
    const int lane = tid & 31;
    const int warp = tid >> 5;
    const int wm   = warp >> 2;
    const int wn   = warp & 3;
    const int m0   = blockIdx.y * GBM;
    const int n0   = blockIdx.x * GBN;

    float d[4][4][4];
    #pragma unroll
    for (int i = 0; i < 4; i++)
        #pragma unroll
        for (int j = 0; j < 4; j++)
            #pragma unroll
            for (int c = 0; c < 4; c++) d[i][j][c] = 0.f;

    // ldmatrix per-lane base offsets (bytes within each array)
    const unsigned aOff = (unsigned)(((wm * 64 + (lane & 15)) * ASTRIDE + (lane >> 4) * 8) * 2);
    const unsigned bOff = (unsigned)(((lane & 15) * BSTRIDE + wn * 32) * 2);

    // cp.async chunk indices
    const int aCh0 = tid, aCh1 = tid + 256;        // 512 chunks: r=ch>>2, c=ch&3
    const int bCh0 = tid, bCh1 = tid + 256;        // 512 chunks: r=ch>>4, c=ch&15

    #define GEMM_ISSUE(it, s) {                                                   \
        int k0_ = (it) * GBK;                                                     \
        unsigned aH_ = base + G_AH(s) * 4, aL_ = base + G_AL(s) * 4;              \
        unsigned bH_ = base + G_BH(s) * 4, bL_ = base + G_BL(s) * 4;              \
        {   int r = aCh0 >> 2, c = aCh0 & 3;                                      \
            unsigned dd = r * 80 + c * 16;                                        \
            size_t so = ((size_t)(m0 + r) * K + k0_ + c * 8) * 2;                 \
            cp16(aH_ + dd, Ah + so); cp16(aL_ + dd, Al + so); }                   \
        {   int r = aCh1 >> 2, c = aCh1 & 3;                                      \
            unsigned dd = r * 80 + c * 16;                                        \
            size_t so = ((size_t)(m0 + r) * K + k0_ + c * 8) * 2;                 \
            cp16(aH_ + dd, Ah + so); cp16(aL_ + dd, Al + so); }                   \
        {   int r = bCh0 >> 4, c = bCh0 & 15;                                     \
            unsigned dd = r * 272 + c * 16;                                       \
            size_t so = ((size_t)(k0_ + r) * N + n0 + c * 8) * 2;                 \
            cp16(bH_ + dd, Bh + so); cp16(bL_ + dd, Bl + so); }                   \
        {   int r = bCh1 >> 4, c = bCh1 & 15;                                     \
            unsigned dd = r * 272 + c * 16;                                       \
            size_t so = ((size_t)(k0_ + r) * N + n0 + c * 8) * 2;                 \
            cp16(bH_ + dd, Bh + so); cp16(bL_ + dd, Bl + so); }                   \
        cp_commit(); }

    const int iters = K / GBK;
    GEMM_ISSUE(0, 0);

    for (int it = 0; it < iters; it++) {
        const int s = it & 1;
        if (it + 1 < iters) {
            GEMM_ISSUE(it + 1, s ^ 1);
            cp_wait<1>();
        } else {
            cp_wait<0>();
        }
        __syncthreads();

        const unsigned aHiB = base + G_AH(s) * 4 + aOff;
        const unsigned aLoB = base + G_AL(s) * 4 + aOff;
        const unsigned bHiB = base + G_BH(s) * 4 + bOff;
        const unsigned bLoB = base + G_BL(s) * 4 + bOff;

        #pragma unroll
        for (int kc = 0; kc < GBK; kc += 16) {
            unsigned ah[4][4], al[4][4], bh[4][2], bl[4][2];
            #pragma unroll
            for (int tm = 0; tm < 4; tm++) {
                unsigned off = tm * (16 * ASTRIDE * 2) + kc * 2;
                ldsm_x4(ah[tm], aHiB + off);
                ldsm_x4(al[tm], aLoB + off);
            }
            #pragma unroll
            for (int tn = 0; tn < 4; tn++) {
                unsigned off = kc * (BSTRIDE * 2) + tn * 16;
                ldsm_x2t(bh[tn], bHiB + off);
                ldsm_x2t(bl[tn], bLoB + off);
            }
            #pragma unroll
            for (int tm = 0; tm < 4; tm++)
                #pragma unroll
                for (int tn = 0; tn < 4; tn++) {
                    mma16816(d[tm][tn], ah[tm], bh[tn]);
                    mma16816(d[tm][tn], ah[tm], bl[tn]);
                    mma16816(d[tm][tn], al[tm], bh[tn]);
                }
        }
        __syncthreads();
    }

    // epilogue
    const int g = lane >> 2, t4 = lane & 3;
    #pragma unroll
    for (int tn = 0; tn < 4; tn++) {
        int col = n0 + wn * 32 + tn * 8 + t4 * 2;
        float bx = bias[col], by = bias[col + 1];
        #pragma unroll
        for (int tm = 0; tm < 4; tm++) {
            int row0 = m0 + wm * 64 + tm * 16 + g;
            float v0 = d[tm][tn][0] + bx, v1 = d[tm][tn][1] + by;
            float v2 = d[tm][tn][2] + bx, v3 = d[tm][tn][3] + by;
            if (SPLIT_OUT) {
                unsigned h_, l_;
                split2(v0, v1, h_, l_);
                size_t idx = ((size_t)row0 * N + col) >> 1;
                Chi[idx] = h_; Clo[idx] = l_;
                split2(v2, v3, h_, l_);
                idx = ((size_t)(row0 + 8) * N + col) >> 1;
                Chi[idx] = h_; Clo[idx] = l_;
            } else {
                *(float2*)(Cf + (size_t)row0 * N + col)       = make_float2(v0, v1);
                *(float2*)(Cf + (size_t)(row0 + 8) * N + col) = make_float2(v2, v3);
            }
        }
    }
}

// ---------------------------------------------------------------------------
// Tensor-core flash attention (causal), bf16 hi/lo inputs, fp32 accumulate.
// 128 queries x 64-key tiles, 8 warps. cp.async double-buffered K/V.
// ---------------------------------------------------------------------------
#define FQ 128
#define FK 64
#define QSTR 136          // bf16 units per row (272 B)

// byte offsets in dynamic smem
#define OFFB_QH 0
#define OFFB_QL 34816
#define OFFB_KV 69632      // per stage: KH +0, KL +17408, VH +34816, VL +52224
#define KV_STAGE 69632
#define FLASH_SMEM (69632 + 2 * 69632)   // 208896 bytes

__global__ void __launch_bounds__(256, 1) flash_mma_kernel(
    const char* __restrict__ qkvh, const char* __restrict__ qkvl,
    unsigned* __restrict__ atth, unsigned* __restrict__ attl)
{
    extern __shared__ unsigned fsm[];
    const unsigned base = smem_u32(fsm);

    const int tid  = threadIdx.x;
    const int lane = tid & 31;
    const int wm   = tid >> 5;
    const int g    = lane >> 2;
    const int t4   = lane & 3;

    const int qi = blockIdx.x;
    const int h  = blockIdx.y;
    const int b  = blockIdx.z;
    const int q0 = qi * FQ;
    const float sc_att = 0.08838834764831844f;  // 1/sqrt(128)

    // ---- async load Q (hi+lo), then KV tile 0 ----
    #pragma unroll
    for (int i = 0; i < 8; i++) {
        int ch = tid + i * 256;         // 0..2047
        int r = ch >> 4, c = ch & 15;
        unsigned dd = (unsigned)(r * 272 + c * 16);
        size_t so = ((size_t)((size_t)b * TSEQ + q0 + r) * 3 * CDIM + h * HD + c * 8) * 2;
        cp16(base + OFFB_QH + dd, qkvh + so);
        cp16(base + OFFB_QL + dd, qkvl + so);
    }
    cp_commit();

    #define KV_ISSUE(j, s) {                                                       \
        unsigned sb = base + OFFB_KV + (s) * KV_STAGE;                             \
        _Pragma("unroll")                                                          \
        for (int i = 0; i < 4; i++) {                                              \
            int ch = tid + i * 256;      /* 0..1023 */                             \
            int r = ch >> 4, c = ch & 15;                                          \
            unsigned dd = (unsigned)(r * 272 + c * 16);                            \
            size_t ro = ((size_t)((size_t)b * TSEQ + (j) * FK + r) * 3 * CDIM      \
                         + h * HD + c * 8) * 2;                                    \
            cp16(sb + dd,         qkvh + ro + CDIM * 2);                           \
            cp16(sb + 17408 + dd, qkvl + ro + CDIM * 2);                           \
            cp16(sb + 34816 + dd, qkvh + ro + 2 * CDIM * 2);                       \
            cp16(sb + 52224 + dd, qkvl + ro + 2 * CDIM * 2);                       \
        }                                                                          \
        cp_commit(); }

    KV_ISSUE(0, 0);
    cp_wait<1>();          // Q group retired
    __syncthreads();

    // hoist Qh A-fragments (8 k-steps)
    unsigned qh[8][4];
    const unsigned aoff = (unsigned)(((wm * 16 + (lane & 15)) * QSTR + (lane >> 4) * 8) * 2);
    #pragma unroll
    for (int ks = 0; ks < 8; ks++)
        ldsm_x4(qh[ks], base + OFFB_QH + aoff + ks * 32);

    float m0r = -INFINITY, m1r = -INFINITY, l0r = 0.f, l1r = 0.f;
    float O[16][4];
    #pragma unroll
    for (int dt = 0; dt < 16; dt++)
        #pragma unroll
        for (int c = 0; c < 4; c++) O[dt][c] = 0.f;

    const unsigned kRowOff = (unsigned)(((lane & 7) * QSTR + ((lane >> 3) & 1) * 8) * 2);
    const unsigned vRowOff = (unsigned)(((lane & 15) * QSTR) * 2);

    const int jmax = 2 * qi + 2;
    for (int j = 0; j < jmax; j++) {
        const int s = j & 1;
        if (j + 1 < jmax) {
            KV_ISSUE(j + 1, s ^ 1);
            cp_wait<1>();
        } else {
            cp_wait<0>();
        }
        __syncthreads();

        const unsigned kHiB = base + OFFB_KV + s * KV_STAGE;
        const unsigned kLoB = kHiB + 17408;
        const unsigned vHiB = kHiB + 34816;
        const unsigned vLoB = kHiB + 52224;

        // ---- S = Q K^T ----
        float S[8][4];
        #pragma unroll
        for (int nt = 0; nt < 8; nt++)
            #pragma unroll
            for (int c = 0; c < 4; c++) S[nt][c] = 0.f;

        #pragma unroll
        for (int ks = 0; ks < 8; ks++) {
            unsigned ql_[4];
            ldsm_x4(ql_, base + OFFB_QL + aoff + ks * 32);
            #pragma unroll
            for (int nt = 0; nt < 8; nt++) {
                unsigned koff = kRowOff + (unsigned)((nt * 8 * QSTR + ks * 16) * 2);
                unsigned kh_[2], kl_[2];
                ldsm_x2(kh_, kHiB + koff);
                ldsm_x2(kl_, kLoB + koff);
                mma16816(S[nt], qh[ks], kh_);
                mma16816(S[nt], qh[ks], kl_);
                mma16816(S[nt], ql_, kh_);
            }
        }

        // scale
        #pragma unroll
        for (int nt = 0; nt < 8; nt++)
            #pragma unroll
            for (int c = 0; c < 4; c++) S[nt][c] *= sc_att;

        // ---- causal mask (near-diagonal tiles only) ----
        const int rg0 = q0 + wm * 16 + g;
        const int rg1 = rg0 + 8;
        if (j * FK + FK - 1 > q0 + wm * 16) {
            #pragma unroll
            for (int nt = 0; nt < 8; nt++) {
                int kg = j * FK + nt * 8 + 2 * t4;
                if (kg     > rg0) S[nt][0] = -INFINITY;
                if (kg + 1 > rg0) S[nt][1] = -INFINITY;
                if (kg     > rg1) S[nt][2] = -INFINITY;
                if (kg + 1 > rg1) S[nt][3] = -INFINITY;
            }
        }

        // ---- online softmax ----
        float mx0 = -INFINITY, mx1 = -INFINITY;
        #pragma unroll
        for (int nt = 0; nt < 8; nt++) {
            mx0 = fmaxf(mx0, fmaxf(S[nt][0], S[nt][1]));
            mx1 = fmaxf(mx1, fmaxf(S[nt][2], S[nt][3]));
        }
        mx0 = fmaxf(mx0, __shfl_xor_sync(0xffffffffu, mx0, 1));
        mx0 = fmaxf(mx0, __shfl_xor_sync(0xffffffffu, mx0, 2));
        mx1 = fmaxf(mx1, __shfl_xor_sync(0xffffffffu, mx1, 1));
        mx1 = fmaxf(mx1, __shfl_xor_sync(0xffffffffu, mx1, 2));
        float mn0 = fmaxf(m0r, mx0), mn1 = fmaxf(m1r, mx1);
        float sc0 = __expf(m0r - mn0), sc1 = __expf(m1r - mn1);
        m0r = mn0; m1r = mn1;

        float sum0 = 0.f, sum1 = 0.f;
        unsigned phi[16], plo[16];
        #pragma unroll
        for (int nt = 0; nt < 8; nt++) {
            float p0 = __expf(S[nt][0] - mn0);
            float p1 = __expf(S[nt][1] - mn0);
            float p2 = __expf(S[nt][2] - mn1);
            float p3 = __expf(S[nt][3] - mn1);
            sum0 += p0 + p1; sum1 += p2 + p3;
            split2(p0, p1, phi[2 * nt],     plo[2 * nt]);
            split2(p2, p3, phi[2 * nt + 1], plo[2 * nt + 1]);
        }
        sum0 += __shfl_xor_sync(0xffffffffu, sum0, 1);
        sum0 += __shfl_xor_sync(0xffffffffu, sum0, 2);
        sum1 += __shfl_xor_sync(0xffffffffu, sum1, 1);
        sum1 += __shfl_xor_sync(0xffffffffu, sum1, 2);
        l0r = l0r * sc0 + sum0;
        l1r = l1r * sc1 + sum1;

        #pragma unroll
        for (int dt = 0; dt < 16; dt++) {
            O[dt][0] *= sc0; O[dt][1] *= sc0;
            O[dt][2] *= sc1; O[dt][3] *= sc1;
        }

        // ---- O += P V ----
        #pragma unroll
        for (int ks = 0; ks < 4; ks++) {
            unsigned pa_h[4] = {phi[4 * ks], phi[4 * ks + 1], phi[4 * ks + 2], phi[4 * ks + 3]};
            unsigned pa_l[4] = {plo[4 * ks], plo[4 * ks + 1], plo[4 * ks + 2], plo[4 * ks + 3]};
            #pragma unroll
            for (int dt = 0; dt < 16; dt++) {
                unsigned voff = vRowOff + (unsigned)((ks * 16 * QSTR + dt * 8) * 2);
                unsigned vh_[2], vl_[2];
                ldsm_x2t(vh_, vHiB + voff);
                ldsm_x2t(vl_, vLoB + voff);
                mma16816(O[dt], pa_h, vh_);
                mma16816(O[dt], pa_h, vl_);
                mma16816(O[dt], pa_l, vh_);
            }
        }
        __syncthreads();
    }

    // ---- epilogue: normalize + split-store att ----
    float inv0 = 1.f / l0r, inv1 = 1.f / l1r;
    const int rg0 = q0 + wm * 16 + g;
    #pragma unroll
    for (int dt = 0; dt < 16; dt++) {
        int col = dt * 8 + 2 * t4;
        unsigned h_, l_;
        split2(O[dt][0] * inv0, O[dt][1] * inv0, h_, l_);
        size_t idx = (((size_t)b * TSEQ + rg0) * CDIM + h * HD + col) >> 1;
        atth[idx] = h_; attl[idx] = l_;
        split2(O[dt][2] * inv1, O[dt][3] * inv1, h_, l_);
        idx = (((size_t)b * TSEQ + rg0 + 8) * CDIM + h * HD + col) >> 1;
        atth[idx] = h_; attl[idx] = l_;
    }
}

// ---------------------------------------------------------------------------
extern "C" void kernel_launch(void* const* d_in, const int* in_sizes, int n_in,
                              void* d_out, int out_size)
{
    const float* x      = (const float*)d_in[0];
    const float* w_attn = (const float*)d_in[1];
    const float* b_attn = (const float*)d_in[2];
    const float* w_proj = (const float*)d_in[3];
    const float* b_proj = (const float*)d_in[4];
    float* out = (float*)d_out;

    unsigned *xh, *xl, *wah, *wal, *wph, *wpl, *qkvh, *qkvl, *atth, *attl;
    cudaGetSymbolAddress((void**)&xh,   g_xh);
    cudaGetSymbolAddress((void**)&xl,   g_xl);
    cudaGetSymbolAddress((void**)&wah,  g_wah);
    cudaGetSymbolAddress((void**)&wal,  g_wal);
    cudaGetSymbolAddress((void**)&wph,  g_wph);
    cudaGetSymbolAddress((void**)&wpl,  g_wpl);
    cudaGetSymbolAddress((void**)&qkvh, g_qkvh);
    cudaGetSymbolAddress((void**)&qkvl, g_qkvl);
    cudaGetSymbolAddress((void**)&atth, g_atth);
    cudaGetSymbolAddress((void**)&attl, g_attl);

    cudaFuncSetAttribute(gemm_bf16_kernel<true>,
                         cudaFuncAttributeMaxDynamicSharedMemorySize, GEMM_SMEM);
    cudaFuncSetAttribute(gemm_bf16_kernel<false>,
                         cudaFuncAttributeMaxDynamicSharedMemorySize, GEMM_SMEM);
    cudaFuncSetAttribute(flash_mma_kernel,
                         cudaFuncAttributeMaxDynamicSharedMemorySize, FLASH_SMEM);

    const int M = BDIM * TSEQ;  // 4096

    // 0) split inputs to bf16 hi/lo
    int n2x = BDIM * TSEQ * CDIM / 2;          // 4194304
    int n2a = CDIM * 3 * CDIM / 2;             // 6291456
    int n2p = CDIM * CDIM / 2;                 // 2097152
    split_kernel<<<(n2x + 255) / 256, 256>>>((const float2*)x,      xh,  xl,  n2x);
    split_kernel<<<(n2a + 255) / 256, 256>>>((const float2*)w_attn, wah, wal, n2a);
    split_kernel<<<(n2p + 255) / 256, 256>>>((const float2*)w_proj, wph, wpl, n2p);

    // 1) QKV = x @ w_attn + b_attn  -> split bf16 qkv
    gemm_bf16_kernel<true><<<dim3(3 * CDIM / GBN, M / GBM), 256, GEMM_SMEM>>>(
        (const char*)xh, (const char*)xl, (const char*)wah, (const char*)wal,
        b_attn, nullptr, qkvh, qkvl, M, 3 * CDIM, CDIM);

    // 2) Flash attention -> split bf16 att
    flash_mma_kernel<<<dim3(TSEQ / FQ, NHEAD, BDIM), 256, FLASH_SMEM>>>(
        (const char*)qkvh, (const char*)qkvl, atth, attl);

    // 3) out = att @ w_proj + b_proj  (fp32 out)
    gemm_bf16_kernel<false><<<dim3(CDIM / GBN, M / GBM), 256, GEMM_SMEM>>>(
        (const char*)atth, (const char*)attl, (const char*)wph, (const char*)wpl,
        b_proj, out, nullptr, nullptr, M, CDIM, CDIM);
}

// round 9
// speedup vs baseline: 1.8512x; 1.8512x over previous
#include <cuda_runtime.h>
#include <cuda_bf16.h>
#include <cuda_fp16.h>
#include <math.h>

#define BDIM  2
#define TSEQ  2048
#define CDIM  2048
#define NHEAD 16
#define HD    128

// Scratch (static device globals — no runtime allocation)
__device__ float g_qkv[(size_t)BDIM * TSEQ * 3 * CDIM];   // [B,T,3C]
__device__ float g_att[(size_t)BDIM * TSEQ * CDIM];       // [B,T,C]

// ---------------- helpers ----------------
__device__ __forceinline__ unsigned smem_u32(const void* p) {
    unsigned a;
    asm("{ .reg .u64 t; cvta.to.shared.u64 t, %1; cvt.u32.u64 %0, t; }"
        : "=r"(a) : "l"(p));
    return a;
}

// pack two fp32 into f16x2 (low 16 = x, high 16 = y)
__device__ __forceinline__ unsigned pack2h(float x, float y) {
    unsigned r;
    asm("cvt.rn.f16x2.f32 %0, %1, %2;" : "=r"(r) : "f"(y), "f"(x));
    return r;
}

// Split two fp32 into packed bf16 hi-pair and lo-pair (residual) — flash kernel.
__device__ __forceinline__ void split2(float x, float y, unsigned& hi, unsigned& lo) {
    unsigned h;
    asm("cvt.rn.bf16x2.f32 %0, %1, %2;" : "=r"(h) : "f"(y), "f"(x));
    float hx = __uint_as_float(h << 16);
    float hy = __uint_as_float(h & 0xffff0000u);
    float rx = x - hx;
    float ry = y - hy;
    unsigned l;
    asm("cvt.rn.bf16x2.f32 %0, %1, %2;" : "=r"(l) : "f"(ry), "f"(rx));
    hi = h; lo = l;
}

// bf16 mma (flash)
__device__ __forceinline__ void mma16816(float* d, const unsigned* a, const unsigned* b) {
    asm("mma.sync.aligned.m16n8k16.row.col.f32.bf16.bf16.f32 "
        "{%0,%1,%2,%3}, {%4,%5,%6,%7}, {%8,%9}, {%0,%1,%2,%3};"
        : "+f"(d[0]), "+f"(d[1]), "+f"(d[2]), "+f"(d[3])
        : "r"(a[0]), "r"(a[1]), "r"(a[2]), "r"(a[3]), "r"(b[0]), "r"(b[1]));
}
// fp16 mma (GEMMs)
__device__ __forceinline__ void mma16816h(float* d, const unsigned* a, const unsigned* b) {
    asm("mma.sync.aligned.m16n8k16.row.col.f32.f16.f16.f32 "
        "{%0,%1,%2,%3}, {%4,%5,%6,%7}, {%8,%9}, {%0,%1,%2,%3};"
        : "+f"(d[0]), "+f"(d[1]), "+f"(d[2]), "+f"(d[3])
        : "r"(a[0]), "r"(a[1]), "r"(a[2]), "r"(a[3]), "r"(b[0]), "r"(b[1]));
}

__device__ __forceinline__ void ldsm_x4(unsigned* r, unsigned addr) {
    asm volatile("ldmatrix.sync.aligned.m8n8.x4.shared.b16 {%0,%1,%2,%3}, [%4];"
                 : "=r"(r[0]), "=r"(r[1]), "=r"(r[2]), "=r"(r[3]) : "r"(addr));
}
__device__ __forceinline__ void ldsm_x2(unsigned* r, unsigned addr) {
    asm volatile("ldmatrix.sync.aligned.m8n8.x2.shared.b16 {%0,%1}, [%2];"
                 : "=r"(r[0]), "=r"(r[1]) : "r"(addr));
}
__device__ __forceinline__ void ldsm_x2t(unsigned* r, unsigned addr) {
    asm volatile("ldmatrix.sync.aligned.m8n8.x2.trans.shared.b16 {%0,%1}, [%2];"
                 : "=r"(r[0]), "=r"(r[1]) : "r"(addr));
}

// ---------------------------------------------------------------------------
// GEMM + bias via single-term fp16 tensor cores (error ~2^-11, within budget).
// Block 128x128, BK=32, 256 threads (8 warps, warp tile 64x32).
// smem: A [128][40 f16], B [32][136 f16] (16B-aligned rows, conflict-free).
// ---------------------------------------------------------------------------
#define GBM 128
#define GBN 128
#define GBK 32
#define ASTRIDE 40    // f16 units
#define BSTRIDE 136   // f16 units

__global__ void __launch_bounds__(256, 2) gemm_f16_kernel(
    const float* __restrict__ A, const float* __restrict__ B,
    const float* __restrict__ bias, float* __restrict__ C,
    int M, int N, int K)
{
    __shared__ unsigned As[GBM * (ASTRIDE / 2)];   // uint = 2 f16
    __shared__ unsigned Bs[GBK * (BSTRIDE / 2)];

    const int tid  = threadIdx.x;
    const int lane = tid & 31;
    const int warp = tid >> 5;
    const int wm   = warp >> 2;      // 0..1
    const int wn   = warp & 3;       // 0..3
    const int m0   = blockIdx.y * GBM;
    const int n0   = blockIdx.x * GBN;

    float d[4][4][4];
    #pragma unroll
    for (int i = 0; i < 4; i++)
        #pragma unroll
        for (int j = 0; j < 4; j++)
            #pragma unroll
            for (int c = 0; c < 4; c++) d[i][j][c] = 0.f;

    // staging indices
    const int a_c4 = tid & 7;        // float4 col in A tile (BK/4=8)
    const int a_r  = tid >> 3;       // 0..31, rows +32*l
    const int b_c4 = tid & 31;       // float4 col in B tile (BN/4=32)
    const int b_r  = tid >> 5;       // 0..7, rows +8*l

    float4 stA[4], stB[4];
    #pragma unroll
    for (int l = 0; l < 4; l++)
        stA[l] = *(const float4*)(A + (size_t)(m0 + a_r + 32 * l) * K + a_c4 * 4);
    #pragma unroll
    for (int l = 0; l < 4; l++)
        stB[l] = *(const float4*)(B + (size_t)(b_r + 8 * l) * N + n0 + b_c4 * 4);

    // ldmatrix per-lane base offsets (bytes)
    const unsigned aOff = (unsigned)(((wm * 64 + (lane & 15)) * ASTRIDE + (lane >> 4) * 8) * 2);
    const unsigned bOff = (unsigned)(((lane & 15) * BSTRIDE + wn * 32) * 2);

    const unsigned aB = smem_u32(As) + aOff;
    const unsigned bB = smem_u32(Bs) + bOff;

    const int iters = K / GBK;
    for (int it = 0; it < iters; it++) {
        // convert + store staged tile to smem (fp16)
        #pragma unroll
        for (int l = 0; l < 4; l++) {
            int ui = (a_r + 32 * l) * (ASTRIDE / 2) + a_c4 * 2;
            As[ui]     = pack2h(stA[l].x, stA[l].y);
            As[ui + 1] = pack2h(stA[l].z, stA[l].w);
        }
        #pragma unroll
        for (int l = 0; l < 4; l++) {
            int ui = (b_r + 8 * l) * (BSTRIDE / 2) + b_c4 * 2;
            Bs[ui]     = pack2h(stB[l].x, stB[l].y);
            Bs[ui + 1] = pack2h(stB[l].z, stB[l].w);
        }
        __syncthreads();

        // prefetch next tile
        if (it + 1 < iters) {
            int k0 = (it + 1) * GBK;
            #pragma unroll
            for (int l = 0; l < 4; l++)
                stA[l] = *(const float4*)(A + (size_t)(m0 + a_r + 32 * l) * K + k0 + a_c4 * 4);
            #pragma unroll
            for (int l = 0; l < 4; l++)
                stB[l] = *(const float4*)(B + (size_t)(k0 + b_r + 8 * l) * N + n0 + b_c4 * 4);
        }

        #pragma unroll
        for (int kc = 0; kc < GBK; kc += 16) {
            unsigned ah[4][4], bh[4][2];
            #pragma unroll
            for (int tm = 0; tm < 4; tm++)
                ldsm_x4(ah[tm], aB + tm * (16 * ASTRIDE * 2) + kc * 2);
            #pragma unroll
            for (int tn = 0; tn < 4; tn++)
                ldsm_x2t(bh[tn], bB + kc * (BSTRIDE * 2) + tn * 16);
            #pragma unroll
            for (int tm = 0; tm < 4; tm++)
                #pragma unroll
                for (int tn = 0; tn < 4; tn++)
                    mma16816h(d[tm][tn], ah[tm], bh[tn]);
        }
        __syncthreads();
    }

    // epilogue: bias + store
    const int g = lane >> 2, t4 = lane & 3;
    #pragma unroll
    for (int tn = 0; tn < 4; tn++) {
        int col = n0 + wn * 32 + tn * 8 + t4 * 2;
        float bx = bias[col], by = bias[col + 1];
        #pragma unroll
        for (int tm = 0; tm < 4; tm++) {
            int row0 = m0 + wm * 64 + tm * 16 + g;
            float2 s0 = make_float2(d[tm][tn][0] + bx, d[tm][tn][1] + by);
            float2 s1 = make_float2(d[tm][tn][2] + bx, d[tm][tn][3] + by);
            *(float2*)(C + (size_t)row0 * N + col) = s0;
            *(float2*)(C + (size_t)(row0 + 8) * N + col) = s1;
        }
    }
}

// ---------------------------------------------------------------------------
// Tensor-core flash attention (causal), bf16 3-term split, fp32 accumulate.
// (round-5 version, known good: 128 queries x 64-key tiles, 8 warps)
// ---------------------------------------------------------------------------
#define FQ 128
#define FK 64
#define QSTR 136          // bf16 units per row
#define QSTRU 68          // uint units per row

#define OFF_QH 0
#define OFF_QL (128 * QSTRU)
#define OFF_KH (OFF_QL + 128 * QSTRU)
#define OFF_KL (OFF_KH + 64 * QSTRU)
#define OFF_VH (OFF_KL + 64 * QSTRU)
#define OFF_VL (OFF_VH + 64 * QSTRU)
#define FLASH_SMEM ((OFF_VL + 64 * QSTRU) * 4)   // 139264 bytes

__global__ void __launch_bounds__(256, 1) flash_mma_kernel(
    const float* __restrict__ qkv, float* __restrict__ out)
{
    extern __shared__ unsigned fsm[];
    const unsigned base = smem_u32(fsm);

    const int tid  = threadIdx.x;
    const int lane = tid & 31;
    const int wm   = tid >> 5;          // 0..7 : 16 query rows each
    const int g    = lane >> 2;
    const int t4   = lane & 3;

    const int qi = blockIdx.x;
    const int h  = blockIdx.y;
    const int b  = blockIdx.z;
    const int q0 = qi * FQ;
    const float scale_q = 0.08838834764831844f;  // 1/sqrt(128)

    const float* qb = qkv + (size_t)b * TSEQ * 3 * CDIM + h * HD;
    const float* kb = qb + CDIM;
    const float* vb = qb + 2 * CDIM;

    // ---- load + split Q tile (128 x 128), pre-scaled ----
    #pragma unroll
    for (int l = 0; l < 16; l++) {
        int lin = tid + l * 256;
        int r   = lin >> 5;
        int c   = lin & 31;
        float4 v = *(const float4*)(qb + (size_t)(q0 + r) * 3 * CDIM + c * 4);
        unsigned h0, l0, h1, l1;
        split2(v.x * scale_q, v.y * scale_q, h0, l0);
        split2(v.z * scale_q, v.w * scale_q, h1, l1);
        int ui = r * QSTRU + c * 2;
        fsm[OFF_QH + ui] = h0; fsm[OFF_QH + ui + 1] = h1;
        fsm[OFF_QL + ui] = l0; fsm[OFF_QL + ui + 1] = l1;
    }
    __syncthreads();

    unsigned qh[8][4];
    const unsigned aoff = (unsigned)(((wm * 16 + (lane & 15)) * QSTR + (lane >> 4) * 8) * 2);
    #pragma unroll
    for (int ks = 0; ks < 8; ks++)
        ldsm_x4(qh[ks], base + OFF_QH * 4 + aoff + ks * 32);

    float m0r = -INFINITY, m1r = -INFINITY, l0r = 0.f, l1r = 0.f;
    float O[16][4];
    #pragma unroll
    for (int dt = 0; dt < 16; dt++)
        #pragma unroll
        for (int c = 0; c < 4; c++) O[dt][c] = 0.f;

    const int jmax = 2 * qi + 2;
    for (int j = 0; j < jmax; j++) {
        __syncthreads();
        #pragma unroll
        for (int l = 0; l < 8; l++) {
            int lin = tid + l * 256;
            int r   = lin >> 5;
            int c   = lin & 31;
            size_t goff = (size_t)(j * FK + r) * 3 * CDIM + c * 4;
            int ui = r * QSTRU + c * 2;
            float4 kv = *(const float4*)(kb + goff);
            unsigned h0, lo0, h1, lo1;
            split2(kv.x, kv.y, h0, lo0);
            split2(kv.z, kv.w, h1, lo1);
            fsm[OFF_KH + ui] = h0; fsm[OFF_KH + ui + 1] = h1;
            fsm[OFF_KL + ui] = lo0; fsm[OFF_KL + ui + 1] = lo1;
            float4 vv = *(const float4*)(vb + goff);
            split2(vv.x, vv.y, h0, lo0);
            split2(vv.z, vv.w, h1, lo1);
            fsm[OFF_VH + ui] = h0; fsm[OFF_VH + ui + 1] = h1;
            fsm[OFF_VL + ui] = lo0; fsm[OFF_VL + ui + 1] = lo1;
        }
        __syncthreads();

        float S[8][4];
        #pragma unroll
        for (int nt = 0; nt < 8; nt++)
            #pragma unroll
            for (int c = 0; c < 4; c++) S[nt][c] = 0.f;

        const unsigned kRowOff = (unsigned)(((lane & 7) * QSTR + ((lane >> 3) & 1) * 8) * 2);
        #pragma unroll
        for (int ks = 0; ks < 8; ks++) {
            unsigned ql_[4];
            ldsm_x4(ql_, base + OFF_QL * 4 + aoff + ks * 32);
            #pragma unroll
            for (int nt = 0; nt < 8; nt++) {
                unsigned koff = kRowOff + (unsigned)((nt * 8 * QSTR + ks * 16) * 2);
                unsigned kh_[2], kl_[2];
                ldsm_x2(kh_, base + OFF_KH * 4 + koff);
                ldsm_x2(kl_, base + OFF_KL * 4 + koff);
                mma16816(S[nt], qh[ks], kh_);
                mma16816(S[nt], qh[ks], kl_);
                mma16816(S[nt], ql_, kh_);
            }
        }

        const int rg0 = q0 + wm * 16 + g;
        const int rg1 = rg0 + 8;
        if (j * FK + FK - 1 > q0 + wm * 16) {
            #pragma unroll
            for (int nt = 0; nt < 8; nt++) {
                int kg = j * FK + nt * 8 + 2 * t4;
                if (kg     > rg0) S[nt][0] = -INFINITY;
                if (kg + 1 > rg0) S[nt][1] = -INFINITY;
                if (kg     > rg1) S[nt][2] = -INFINITY;
                if (kg + 1 > rg1) S[nt][3] = -INFINITY;
            }
        }

        float mx0 = -INFINITY, mx1 = -INFINITY;
        #pragma unroll
        for (int nt = 0; nt < 8; nt++) {
            mx0 = fmaxf(mx0, fmaxf(S[nt][0], S[nt][1]));
            mx1 = fmaxf(mx1, fmaxf(S[nt][2], S[nt][3]));
        }
        mx0 = fmaxf(mx0, __shfl_xor_sync(0xffffffffu, mx0, 1));
        mx0 = fmaxf(mx0, __shfl_xor_sync(0xffffffffu, mx0, 2));
        mx1 = fmaxf(mx1, __shfl_xor_sync(0xffffffffu, mx1, 1));
        mx1 = fmaxf(mx1, __shfl_xor_sync(0xffffffffu, mx1, 2));
        float mn0 = fmaxf(m0r, mx0), mn1 = fmaxf(m1r, mx1);
        float sc0 = __expf(m0r - mn0), sc1 = __expf(m1r - mn1);
        m0r = mn0; m1r = mn1;

        float sum0 = 0.f, sum1 = 0.f;
        unsigned phi[16], plo[16];
        #pragma unroll
        for (int nt = 0; nt < 8; nt++) {
            float p0 = __expf(S[nt][0] - mn0);
            float p1 = __expf(S[nt][1] - mn0);
            float p2 = __expf(S[nt][2] - mn1);
            float p3 = __expf(S[nt][3] - mn1);
            sum0 += p0 + p1; sum1 += p2 + p3;
            split2(p0, p1, phi[2 * nt],     plo[2 * nt]);
            split2(p2, p3, phi[2 * nt + 1], plo[2 * nt + 1]);
        }
        sum0 += __shfl_xor_sync(0xffffffffu, sum0, 1);
        sum0 += __shfl_xor_sync(0xffffffffu, sum0, 2);
        sum1 += __shfl_xor_sync(0xffffffffu, sum1, 1);
        sum1 += __shfl_xor_sync(0xffffffffu, sum1, 2);
        l0r = l0r * sc0 + sum0;
        l1r = l1r * sc1 + sum1;

        #pragma unroll
        for (int dt = 0; dt < 16; dt++) {
            O[dt][0] *= sc0; O[dt][1] *= sc0;
            O[dt][2] *= sc1; O[dt][3] *= sc1;
        }

        const unsigned vRowOff = (unsigned)(((lane & 15) * QSTR) * 2);
        #pragma unroll
        for (int ks = 0; ks < 4; ks++) {
            unsigned pa_h[4] = {phi[4 * ks], phi[4 * ks + 1], phi[4 * ks + 2], phi[4 * ks + 3]};
            unsigned pa_l[4] = {plo[4 * ks], plo[4 * ks + 1], plo[4 * ks + 2], plo[4 * ks + 3]};
            #pragma unroll
            for (int dt = 0; dt < 16; dt++) {
                unsigned voff = vRowOff + (unsigned)((ks * 16 * QSTR + dt * 8) * 2);
                unsigned vh_[2], vl_[2];
                ldsm_x2t(vh_, base + OFF_VH * 4 + voff);
                ldsm_x2t(vl_, base + OFF_VL * 4 + voff);
                mma16816(O[dt], pa_h, vh_);
                mma16816(O[dt], pa_h, vl_);
                mma16816(O[dt], pa_l, vh_);
            }
        }
    }

    float inv0 = 1.f / l0r, inv1 = 1.f / l1r;
    const int rg0 = q0 + wm * 16 + g;
    float* ob = out + ((size_t)b * TSEQ) * CDIM + h * HD;
    #pragma unroll
    for (int dt = 0; dt < 16; dt++) {
        int col = dt * 8 + 2 * t4;
        *(float2*)(ob + (size_t)rg0 * CDIM + col) =
            make_float2(O[dt][0] * inv0, O[dt][1] * inv0);
        *(float2*)(ob + (size_t)(rg0 + 8) * CDIM + col) =
            make_float2(O[dt][2] * inv1, O[dt][3] * inv1);
    }
}

// ---------------------------------------------------------------------------
extern "C" void kernel_launch(void* const* d_in, const int* in_sizes, int n_in,
                              void* d_out, int out_size)
{
    const float* x      = (const float*)d_in[0];
    const float* w_attn = (const float*)d_in[1];
    const float* b_attn = (const float*)d_in[2];
    const float* w_proj = (const float*)d_in[3];
    const float* b_proj = (const float*)d_in[4];
    float* out = (float*)d_out;

    float *qkv, *att;
    cudaGetSymbolAddress((void**)&qkv, g_qkv);
    cudaGetSymbolAddress((void**)&att, g_att);

    cudaFuncSetAttribute(flash_mma_kernel,
                         cudaFuncAttributeMaxDynamicSharedMemorySize, FLASH_SMEM);

    const int M = BDIM * TSEQ;  // 4096

    // 1) QKV = x @ w_attn + b_attn           [4096, 6144]  (fp16 1-term)
    gemm_f16_kernel<<<dim3(3 * CDIM / GBN, M / GBM), 256>>>(
        x, w_attn, b_attn, qkv, M, 3 * CDIM, CDIM);

    // 2) Flash attention (bf16 3-term) -> g_att
    flash_mma_kernel<<<dim3(TSEQ / FQ, NHEAD, BDIM), 256, FLASH_SMEM>>>(qkv, att);

    // 3) out = att @ w_proj + b_proj         [4096, 2048]  (fp16 1-term)
    gemm_f16_kernel<<<dim3(CDIM / GBN, M / GBM), 256>>>(
        att, w_proj, b_proj, out, M, CDIM, CDIM);
}

// round 11
// speedup vs baseline: 2.0303x; 1.0968x over previous
#include <cuda_runtime.h>
#include <cuda_bf16.h>
#include <cuda_fp16.h>
#include <math.h>

#define BDIM  2
#define TSEQ  2048
#define CDIM  2048
#define NHEAD 16
#define HD    128

// ---------------- device-global scratch (no runtime allocation) ----------------
__device__ unsigned g_xh [(size_t)BDIM * TSEQ * CDIM / 2];      // x fp16 pairs
__device__ unsigned g_wah[(size_t)CDIM * 3 * CDIM / 2];         // w_attn fp16 pairs
__device__ unsigned g_wph[(size_t)CDIM * CDIM / 2];             // w_proj fp16 pairs
__device__ float    g_qkv[(size_t)BDIM * TSEQ * 3 * CDIM];      // qkv fp32
__device__ unsigned g_att[(size_t)BDIM * TSEQ * CDIM / 2];      // att fp16 pairs

// ---------------- helpers ----------------
__device__ __forceinline__ unsigned smem_u32(const void* p) {
    unsigned a;
    asm("{ .reg .u64 t; cvta.to.shared.u64 t, %1; cvt.u32.u64 %0, t; }"
        : "=r"(a) : "l"(p));
    return a;
}

// pack two fp32 into f16x2 (low 16 = x, high 16 = y)
__device__ __forceinline__ unsigned pack2h(float x, float y) {
    unsigned r;
    asm("cvt.rn.f16x2.f32 %0, %1, %2;" : "=r"(r) : "f"(y), "f"(x));
    return r;
}

// Split two fp32 into packed bf16 hi-pair and lo-pair (residual) — flash kernel.
__device__ __forceinline__ void split2(float x, float y, unsigned& hi, unsigned& lo) {
    unsigned h;
    asm("cvt.rn.bf16x2.f32 %0, %1, %2;" : "=r"(h) : "f"(y), "f"(x));
    float hx = __uint_as_float(h << 16);
    float hy = __uint_as_float(h & 0xffff0000u);
    float rx = x - hx;
    float ry = y - hy;
    unsigned l;
    asm("cvt.rn.bf16x2.f32 %0, %1, %2;" : "=r"(l) : "f"(ry), "f"(rx));
    hi = h; lo = l;
}

// bf16 mma (flash)
__device__ __forceinline__ void mma16816(float* d, const unsigned* a, const unsigned* b) {
    asm("mma.sync.aligned.m16n8k16.row.col.f32.bf16.bf16.f32 "
        "{%0,%1,%2,%3}, {%4,%5,%6,%7}, {%8,%9}, {%0,%1,%2,%3};"
        : "+f"(d[0]), "+f"(d[1]), "+f"(d[2]), "+f"(d[3])
        : "r"(a[0]), "r"(a[1]), "r"(a[2]), "r"(a[3]), "r"(b[0]), "r"(b[1]));
}
// fp16 mma (GEMMs)
__device__ __forceinline__ void mma16816h(float* d, const unsigned* a, const unsigned* b) {
    asm("mma.sync.aligned.m16n8k16.row.col.f32.f16.f16.f32 "
        "{%0,%1,%2,%3}, {%4,%5,%6,%7}, {%8,%9}, {%0,%1,%2,%3};"
        : "+f"(d[0]), "+f"(d[1]), "+f"(d[2]), "+f"(d[3])
        : "r"(a[0]), "r"(a[1]), "r"(a[2]), "r"(a[3]), "r"(b[0]), "r"(b[1]));
}

__device__ __forceinline__ void ldsm_x4(unsigned* r, unsigned addr) {
    asm volatile("ldmatrix.sync.aligned.m8n8.x4.shared.b16 {%0,%1,%2,%3}, [%4];"
                 : "=r"(r[0]), "=r"(r[1]), "=r"(r[2]), "=r"(r[3]) : "r"(addr));
}
__device__ __forceinline__ void ldsm_x4t(unsigned* r, unsigned addr) {
    asm volatile("ldmatrix.sync.aligned.m8n8.x4.trans.shared.b16 {%0,%1,%2,%3}, [%4];"
                 : "=r"(r[0]), "=r"(r[1]), "=r"(r[2]), "=r"(r[3]) : "r"(addr));
}

__device__ __forceinline__ void cp16(unsigned dst, const void* src) {
    asm volatile("cp.async.cg.shared.global [%0], [%1], 16;" :: "r"(dst), "l"(src) : "memory");
}
__device__ __forceinline__ void cp_commit() {
    asm volatile("cp.async.commit_group;" ::: "memory");
}
template<int N> __device__ __forceinline__ void cp_wait() {
    asm volatile("cp.async.wait_group %0;" :: "n"(N) : "memory");
}

// ---------------------------------------------------------------------------
// fp32 -> fp16 pair conversion (one-time preprocessing)
// ---------------------------------------------------------------------------
__global__ void f2h_kernel(const float2* __restrict__ in, unsigned* __restrict__ out, int n2)
{
    int i = blockIdx.x * blockDim.x + threadIdx.x;
    if (i < n2) {
        float2 v = in[i];
        out[i] = pack2h(v.x, v.y);
    }
}

// ---------------------------------------------------------------------------
// fp16-in GEMM + bias (fp32 accumulate, fp32 out). cp.async 2-stage pipeline.
// Block 128x128, BK=32, 256 threads (8 warps, warp tile 64x32), 2 CTAs/SM.
// ---------------------------------------------------------------------------
#define GBM 128
#define GBN 128
#define GBK 32
#define ASTRIDE 40      // f16 units per A row (80 B)
#define BSTRIDE 136     // f16 units per B row (272 B)
#define ABYTES (GBM * ASTRIDE * 2)     // 10240
#define BBYTES (GBK * BSTRIDE * 2)     // 8704
#define STAGEB (ABYTES + BBYTES)       // 18944
#define GSMEM  (2 * STAGEB)            // 37888

__global__ void __launch_bounds__(256, 2) gemm_f16cp_kernel(
    const __half* __restrict__ A, const __half* __restrict__ B,
    const float* __restrict__ bias, float* __restrict__ C,
    int M, int N, int K)
{
    extern __shared__ char gsm[];
    const unsigned base = smem_u32(gsm);

    const int tid  = threadIdx.x;
    const int lane = tid & 31;
    const int warp = tid >> 5;
    const int wm   = warp >> 2;      // 0..1
    const int wn   = warp & 3;       // 0..3
    const int m0   = blockIdx.y * GBM;
    const int n0   = blockIdx.x * GBN;

    float d[4][4][4];
    #pragma unroll
    for (int i = 0; i < 4; i++)
        #pragma unroll
        for (int j = 0; j < 4; j++)
            #pragma unroll
            for (int c = 0; c < 4; c++) d[i][j][c] = 0.f;

    // ldmatrix per-lane offsets (bytes, relative to stage base)
    const unsigned aOff = (unsigned)(((wm * 64 + (lane & 15)) * ASTRIDE + (lane >> 4) * 8) * 2);
    const unsigned bOff = (unsigned)(((lane & 15) * BSTRIDE + wn * 32 + ((lane >> 4) & 1) * 8) * 2);

    auto issue = [&](int it, int s) {
        int k0 = it * GBK;
        unsigned st = base + s * STAGEB;
        {   int r = tid >> 2, c = tid & 3;                     // A chunks 0..255
            cp16(st + r * 80 + c * 16, A + (size_t)(m0 + r) * K + k0 + c * 8); }
        {   int ch = tid + 256; int r = ch >> 2, c = ch & 3;   // A chunks 256..511
            cp16(st + r * 80 + c * 16, A + (size_t)(m0 + r) * K + k0 + c * 8); }
        {   int r = tid >> 4, c = tid & 15;                    // B chunks 0..255
            cp16(st + ABYTES + r * 272 + c * 16, B + (size_t)(k0 + r) * N + n0 + c * 8); }
        {   int ch = tid + 256; int r = ch >> 4, c = ch & 15;  // B chunks 256..511
            cp16(st + ABYTES + r * 272 + c * 16, B + (size_t)(k0 + r) * N + n0 + c * 8); }
        cp_commit();
    };

    const int iters = K / GBK;
    issue(0, 0);

    for (int it = 0; it < iters; it++) {
        const int s = it & 1;
        if (it + 1 < iters) {
            issue(it + 1, s ^ 1);
            cp_wait<1>();
        } else {
            cp_wait<0>();
        }
        __syncthreads();

        const unsigned aB = base + s * STAGEB + aOff;
        const unsigned bB = base + s * STAGEB + ABYTES + bOff;

        #pragma unroll
        for (int kc = 0; kc < GBK; kc += 16) {
            unsigned ah[4][4], bh[2][4];
            #pragma unroll
            for (int tm = 0; tm < 4; tm++)
                ldsm_x4(ah[tm], aB + tm * (16 * ASTRIDE * 2) + kc * 2);
            #pragma unroll
            for (int t2 = 0; t2 < 2; t2++)
                ldsm_x4t(bh[t2], bB + kc * (BSTRIDE * 2) + t2 * 32);
            #pragma unroll
            for (int tm = 0; tm < 4; tm++)
                #pragma unroll
                for (int tn = 0; tn < 4; tn++)
                    mma16816h(d[tm][tn], ah[tm], bh[tn >> 1] + (tn & 1) * 2);
        }
        __syncthreads();
    }

    // epilogue: bias + fp32 store
    const int g = lane >> 2, t4 = lane & 3;
    #pragma unroll
    for (int tn = 0; tn < 4; tn++) {
        int col = n0 + wn * 32 + tn * 8 + t4 * 2;
        float bx = bias[col], by = bias[col + 1];
        #pragma unroll
        for (int tm = 0; tm < 4; tm++) {
            int row0 = m0 + wm * 64 + tm * 16 + g;
            *(float2*)(C + (size_t)row0 * N + col) =
                make_float2(d[tm][tn][0] + bx, d[tm][tn][1] + by);
            *(float2*)(C + (size_t)(row0 + 8) * N + col) =
                make_float2(d[tm][tn][2] + bx, d[tm][tn][3] + by);
        }
    }
}

// ---------------------------------------------------------------------------
// Tensor-core flash attention (causal), bf16 3-term split, fp32 accumulate.
// 128 queries x 64-key tiles, 8 warps. x4-batched K/V ldsm; fp16 att output.
// Heavy (high-qi) blocks launch first (reversed mapping).
// ---------------------------------------------------------------------------
#define FQ 128
#define FK 64
#define QSTR 136          // bf16 units per row
#define QSTRU 68          // uint units per row

#define OFF_QH 0
#define OFF_QL (128 * QSTRU)
#define OFF_KH (OFF_QL + 128 * QSTRU)
#define OFF_KL (OFF_KH + 64 * QSTRU)
#define OFF_VH (OFF_KL + 64 * QSTRU)
#define OFF_VL (OFF_VH + 64 * QSTRU)
#define FLASH_SMEM ((OFF_VL + 64 * QSTRU) * 4)   // 139264 bytes

__global__ void __launch_bounds__(256, 1) flash_mma_kernel(
    const float* __restrict__ qkv, unsigned* __restrict__ att)
{
    extern __shared__ unsigned fsm[];
    const unsigned base = smem_u32(fsm);

    const int tid  = threadIdx.x;
    const int lane = tid & 31;
    const int wm   = tid >> 5;          // 0..7 : 16 query rows each
    const int g    = lane >> 2;
    const int t4   = lane & 3;

    const int qi = (int)gridDim.x - 1 - (int)blockIdx.x;   // heavy blocks first
    const int h  = blockIdx.y;
    const int b  = blockIdx.z;
    const int q0 = qi * FQ;
    const float scale_q = 0.08838834764831844f;  // 1/sqrt(128)

    const float* qb = qkv + (size_t)b * TSEQ * 3 * CDIM + h * HD;
    const float* kb = qb + CDIM;
    const float* vb = qb + 2 * CDIM;

    // ---- load + split Q tile (128 x 128), pre-scaled ----
    #pragma unroll
    for (int l = 0; l < 16; l++) {
        int lin = tid + l * 256;
        int r   = lin >> 5;
        int c   = lin & 31;
        float4 v = *(const float4*)(qb + (size_t)(q0 + r) * 3 * CDIM + c * 4);
        unsigned h0, l0, h1, l1;
        split2(v.x * scale_q, v.y * scale_q, h0, l0);
        split2(v.z * scale_q, v.w * scale_q, h1, l1);
        int ui = r * QSTRU + c * 2;
        fsm[OFF_QH + ui] = h0; fsm[OFF_QH + ui + 1] = h1;
        fsm[OFF_QL + ui] = l0; fsm[OFF_QL + ui + 1] = l1;
    }
    __syncthreads();

    unsigned qh[8][4];
    const unsigned aoff = (unsigned)(((wm * 16 + (lane & 15)) * QSTR + (lane >> 4) * 8) * 2);
    #pragma unroll
    for (int ks = 0; ks < 8; ks++)
        ldsm_x4(qh[ks], base + OFF_QH * 4 + aoff + ks * 32);

    float m0r = -INFINITY, m1r = -INFINITY, l0r = 0.f, l1r = 0.f;
    float O[16][4];
    #pragma unroll
    for (int dt = 0; dt < 16; dt++)
        #pragma unroll
        for (int c = 0; c < 4; c++) O[dt][c] = 0.f;

    // x4 K: lanes 0-7 (n+0..7, kc), 8-15 (n+0..7, kc+8), 16-23 (n+8..15, kc), 24-31 (n+8..15, kc+8)
    const unsigned k4Off = (unsigned)(
        (((lane & 7) + ((lane >> 4) & 1) * 8) * QSTR + ((lane >> 3) & 1) * 8) * 2);
    // x4t V: lanes 0-15 (k rows, d+0..7), 16-31 (k rows, d+8..15)
    const unsigned v4Off = (unsigned)(
        ((lane & 15) * QSTR + ((lane >> 4) & 1) * 8) * 2);

    const int jmax = 2 * qi + 2;
    for (int j = 0; j < jmax; j++) {
        __syncthreads();
        #pragma unroll
        for (int l = 0; l < 8; l++) {
            int lin = tid + l * 256;
            int r   = lin >> 5;
            int c   = lin & 31;
            size_t goff = (size_t)(j * FK + r) * 3 * CDIM + c * 4;
            int ui = r * QSTRU + c * 2;
            float4 kv = *(const float4*)(kb + goff);
            unsigned h0, lo0, h1, lo1;
            split2(kv.x, kv.y, h0, lo0);
            split2(kv.z, kv.w, h1, lo1);
            fsm[OFF_KH + ui] = h0; fsm[OFF_KH + ui + 1] = h1;
            fsm[OFF_KL + ui] = lo0; fsm[OFF_KL + ui + 1] = lo1;
            float4 vv = *(const float4*)(vb + goff);
            split2(vv.x, vv.y, h0, lo0);
            split2(vv.z, vv.w, h1, lo1);
            fsm[OFF_VH + ui] = h0; fsm[OFF_VH + ui + 1] = h1;
            fsm[OFF_VL + ui] = lo0; fsm[OFF_VL + ui + 1] = lo1;
        }
        __syncthreads();

        // ---- S = Q K^T ----
        float S[8][4];
        #pragma unroll
        for (int nt = 0; nt < 8; nt++)
            #pragma unroll
            for (int c = 0; c < 4; c++) S[nt][c] = 0.f;

        #pragma unroll
        for (int ks = 0; ks < 8; ks++) {
            unsigned ql_[4];
            ldsm_x4(ql_, base + OFF_QL * 4 + aoff + ks * 32);
            #pragma unroll
            for (int nt = 0; nt < 8; nt += 2) {
                unsigned koff = k4Off + (unsigned)((nt * 8 * QSTR + ks * 16) * 2);
                unsigned kh4[4], kl4[4];
                ldsm_x4(kh4, base + OFF_KH * 4 + koff);
                ldsm_x4(kl4, base + OFF_KL * 4 + koff);
                mma16816(S[nt],     qh[ks], kh4);
                mma16816(S[nt],     qh[ks], kl4);
                mma16816(S[nt],     ql_,    kh4);
                mma16816(S[nt + 1], qh[ks], kh4 + 2);
                mma16816(S[nt + 1], qh[ks], kl4 + 2);
                mma16816(S[nt + 1], ql_,    kh4 + 2);
            }
        }

        // ---- causal mask (near-diagonal tiles only) ----
        const int rg0 = q0 + wm * 16 + g;
        const int rg1 = rg0 + 8;
        if (j * FK + FK - 1 > q0 + wm * 16) {
            #pragma unroll
            for (int nt = 0; nt < 8; nt++) {
                int kg = j * FK + nt * 8 + 2 * t4;
                if (kg     > rg0) S[nt][0] = -INFINITY;
                if (kg + 1 > rg0) S[nt][1] = -INFINITY;
                if (kg     > rg1) S[nt][2] = -INFINITY;
                if (kg + 1 > rg1) S[nt][3] = -INFINITY;
            }
        }

        // ---- online softmax ----
        float mx0 = -INFINITY, mx1 = -INFINITY;
        #pragma unroll
        for (int nt = 0; nt < 8; nt++) {
            mx0 = fmaxf(mx0, fmaxf(S[nt][0], S[nt][1]));
            mx1 = fmaxf(mx1, fmaxf(S[nt][2], S[nt][3]));
        }
        mx0 = fmaxf(mx0, __shfl_xor_sync(0xffffffffu, mx0, 1));
        mx0 = fmaxf(mx0, __shfl_xor_sync(0xffffffffu, mx0, 2));
        mx1 = fmaxf(mx1, __shfl_xor_sync(0xffffffffu, mx1, 1));
        mx1 = fmaxf(mx1, __shfl_xor_sync(0xffffffffu, mx1, 2));
        float mn0 = fmaxf(m0r, mx0), mn1 = fmaxf(m1r, mx1);
        float sc0 = __expf(m0r - mn0), sc1 = __expf(m1r - mn1);
        m0r = mn0; m1r = mn1;

        float sum0 = 0.f, sum1 = 0.f;
        unsigned phi[16], plo[16];
        #pragma unroll
        for (int nt = 0; nt < 8; nt++) {
            float p0 = __expf(S[nt][0] - mn0);
            float p1 = __expf(S[nt][1] - mn0);
            float p2 = __expf(S[nt][2] - mn1);
            float p3 = __expf(S[nt][3] - mn1);
            sum0 += p0 + p1; sum1 += p2 + p3;
            split2(p0, p1, phi[2 * nt],     plo[2 * nt]);
            split2(p2, p3, phi[2 * nt + 1], plo[2 * nt + 1]);
        }
        sum0 += __shfl_xor_sync(0xffffffffu, sum0, 1);
        sum0 += __shfl_xor_sync(0xffffffffu, sum0, 2);
        sum1 += __shfl_xor_sync(0xffffffffu, sum1, 1);
        sum1 += __shfl_xor_sync(0xffffffffu, sum1, 2);
        l0r = l0r * sc0 + sum0;
        l1r = l1r * sc1 + sum1;

        #pragma unroll
        for (int dt = 0; dt < 16; dt++) {
            O[dt][0] *= sc0; O[dt][1] *= sc0;
            O[dt][2] *= sc1; O[dt][3] *= sc1;
        }

        // ---- O += P V ----
        #pragma unroll
        for (int ks = 0; ks < 4; ks++) {
            unsigned pa_h[4] = {phi[4 * ks], phi[4 * ks + 1], phi[4 * ks + 2], phi[4 * ks + 3]};
            unsigned pa_l[4] = {plo[4 * ks], plo[4 * ks + 1], plo[4 * ks + 2], plo[4 * ks + 3]};
            #pragma unroll
            for (int dt = 0; dt < 16; dt += 2) {
                unsigned voff = v4Off + (unsigned)((ks * 16 * QSTR + dt * 8) * 2);
                unsigned vh4[4], vl4[4];
                ldsm_x4t(vh4, base + OFF_VH * 4 + voff);
                ldsm_x4t(vl4, base + OFF_VL * 4 + voff);
                mma16816(O[dt],     pa_h, vh4);
                mma16816(O[dt],     pa_h, vl4);
                mma16816(O[dt],     pa_l, vh4);
                mma16816(O[dt + 1], pa_h, vh4 + 2);
                mma16816(O[dt + 1], pa_h, vl4 + 2);
                mma16816(O[dt + 1], pa_l, vh4 + 2);
            }
        }
    }

    // ---- epilogue: normalize + fp16 store ----
    float inv0 = 1.f / l0r, inv1 = 1.f / l1r;
    const int rg0 = q0 + wm * 16 + g;
    #pragma unroll
    for (int dt = 0; dt < 16; dt++) {
        int col = dt * 8 + 2 * t4;
        size_t idx0 = (((size_t)b * TSEQ + rg0) * CDIM + h * HD + col) >> 1;
        size_t idx1 = (((size_t)b * TSEQ + rg0 + 8) * CDIM + h * HD + col) >> 1;
        att[idx0] = pack2h(O[dt][0] * inv0, O[dt][1] * inv0);
        att[idx1] = pack2h(O[dt][2] * inv1, O[dt][3] * inv1);
    }
}

// ---------------------------------------------------------------------------
extern "C" void kernel_launch(void* const* d_in, const int* in_sizes, int n_in,
                              void* d_out, int out_size)
{
    const float* x      = (const float*)d_in[0];
    const float* w_attn = (const float*)d_in[1];
    const float* b_attn = (const float*)d_in[2];
    const float* w_proj = (const float*)d_in[3];
    const float* b_proj = (const float*)d_in[4];
    float* out = (float*)d_out;

    unsigned *xh, *wah, *wph, *att;
    float *qkv;
    cudaGetSymbolAddress((void**)&xh,  g_xh);
    cudaGetSymbolAddress((void**)&wah, g_wah);
    cudaGetSymbolAddress((void**)&wph, g_wph);
    cudaGetSymbolAddress((void**)&qkv, g_qkv);
    cudaGetSymbolAddress((void**)&att, g_att);

    cudaFuncSetAttribute(gemm_f16cp_kernel,
                         cudaFuncAttributeMaxDynamicSharedMemorySize, GSMEM);
    cudaFuncSetAttribute(flash_mma_kernel,
                         cudaFuncAttributeMaxDynamicSharedMemorySize, FLASH_SMEM);

    const int M = BDIM * TSEQ;  // 4096

    // 0) one-time fp32 -> fp16 conversion (bit-identical to in-kernel cvt.rn)
    int n2x = BDIM * TSEQ * CDIM / 2;
    int n2a = CDIM * 3 * CDIM / 2;
    int n2p = CDIM * CDIM / 2;
    f2h_kernel<<<(n2x + 255) / 256, 256>>>((const float2*)x,      xh,  n2x);
    f2h_kernel<<<(n2a + 255) / 256, 256>>>((const float2*)w_attn, wah, n2a);
    f2h_kernel<<<(n2p + 255) / 256, 256>>>((const float2*)w_proj, wph, n2p);

    // 1) QKV = x @ w_attn + b_attn    (fp16 in, fp32 out)
    gemm_f16cp_kernel<<<dim3(3 * CDIM / GBN, M / GBM), 256, GSMEM>>>(
        (const __half*)xh, (const __half*)wah, b_attn, qkv, M, 3 * CDIM, CDIM);

    // 2) Flash attention (bf16 3-term) -> fp16 att
    flash_mma_kernel<<<dim3(TSEQ / FQ, NHEAD, BDIM), 256, FLASH_SMEM>>>(qkv, att);

    // 3) out = att @ w_proj + b_proj  (fp16 in, fp32 out)
    gemm_f16cp_kernel<<<dim3(CDIM / GBN, M / GBM), 256, GSMEM>>>(
        (const __half*)att, (const __half*)wph, b_proj, out, M, CDIM, CDIM);
}

// round 12
// speedup vs baseline: 2.2586x; 1.1124x over previous
#include <cuda_runtime.h>
#include <cuda_bf16.h>
#include <cuda_fp16.h>
#include <math.h>

#define BDIM  2
#define TSEQ  2048
#define CDIM  2048
#define NHEAD 16
#define HD    128

// ---------------- device-global scratch (no runtime allocation) ----------------
__device__ unsigned g_xh [(size_t)BDIM * TSEQ * CDIM / 2];      // x fp16 pairs
__device__ unsigned g_wah[(size_t)CDIM * 3 * CDIM / 2];         // w_attn fp16 pairs
__device__ unsigned g_wph[(size_t)CDIM * CDIM / 2];             // w_proj fp16 pairs
__device__ float    g_qkv[(size_t)BDIM * TSEQ * 3 * CDIM];      // qkv fp32
__device__ unsigned g_att[(size_t)BDIM * TSEQ * CDIM / 2];      // att fp16 pairs

// ---------------- helpers ----------------
__device__ __forceinline__ unsigned smem_u32(const void* p) {
    unsigned a;
    asm("{ .reg .u64 t; cvta.to.shared.u64 t, %1; cvt.u32.u64 %0, t; }"
        : "=r"(a) : "l"(p));
    return a;
}

// pack two fp32 into f16x2 (low 16 = x, high 16 = y)
__device__ __forceinline__ unsigned pack2h(float x, float y) {
    unsigned r;
    asm("cvt.rn.f16x2.f32 %0, %1, %2;" : "=r"(r) : "f"(y), "f"(x));
    return r;
}

// Split two fp32 into packed bf16 hi-pair and lo-pair (residual).
__device__ __forceinline__ void split2(float x, float y, unsigned& hi, unsigned& lo) {
    unsigned h;
    asm("cvt.rn.bf16x2.f32 %0, %1, %2;" : "=r"(h) : "f"(y), "f"(x));
    float hx = __uint_as_float(h << 16);
    float hy = __uint_as_float(h & 0xffff0000u);
    float rx = x - hx;
    float ry = y - hy;
    unsigned l;
    asm("cvt.rn.bf16x2.f32 %0, %1, %2;" : "=r"(l) : "f"(ry), "f"(rx));
    hi = h; lo = l;
}

// bf16 mma (flash QK)
__device__ __forceinline__ void mma16816(float* d, const unsigned* a, const unsigned* b) {
    asm("mma.sync.aligned.m16n8k16.row.col.f32.bf16.bf16.f32 "
        "{%0,%1,%2,%3}, {%4,%5,%6,%7}, {%8,%9}, {%0,%1,%2,%3};"
        : "+f"(d[0]), "+f"(d[1]), "+f"(d[2]), "+f"(d[3])
        : "r"(a[0]), "r"(a[1]), "r"(a[2]), "r"(a[3]), "r"(b[0]), "r"(b[1]));
}
// fp16 mma (GEMMs + flash PV)
__device__ __forceinline__ void mma16816h(float* d, const unsigned* a, const unsigned* b) {
    asm("mma.sync.aligned.m16n8k16.row.col.f32.f16.f16.f32 "
        "{%0,%1,%2,%3}, {%4,%5,%6,%7}, {%8,%9}, {%0,%1,%2,%3};"
        : "+f"(d[0]), "+f"(d[1]), "+f"(d[2]), "+f"(d[3])
        : "r"(a[0]), "r"(a[1]), "r"(a[2]), "r"(a[3]), "r"(b[0]), "r"(b[1]));
}

__device__ __forceinline__ void ldsm_x4(unsigned* r, unsigned addr) {
    asm volatile("ldmatrix.sync.aligned.m8n8.x4.shared.b16 {%0,%1,%2,%3}, [%4];"
                 : "=r"(r[0]), "=r"(r[1]), "=r"(r[2]), "=r"(r[3]) : "r"(addr));
}
__device__ __forceinline__ void ldsm_x4t(unsigned* r, unsigned addr) {
    asm volatile("ldmatrix.sync.aligned.m8n8.x4.trans.shared.b16 {%0,%1,%2,%3}, [%4];"
                 : "=r"(r[0]), "=r"(r[1]), "=r"(r[2]), "=r"(r[3]) : "r"(addr));
}

__device__ __forceinline__ void cp16(unsigned dst, const void* src) {
    asm volatile("cp.async.cg.shared.global [%0], [%1], 16;" :: "r"(dst), "l"(src) : "memory");
}
__device__ __forceinline__ void cp_commit() {
    asm volatile("cp.async.commit_group;" ::: "memory");
}
template<int N> __device__ __forceinline__ void cp_wait() {
    asm volatile("cp.async.wait_group %0;" :: "n"(N) : "memory");
}

// ---------------------------------------------------------------------------
// fp32 -> fp16 pair conversion (one-time preprocessing)
// ---------------------------------------------------------------------------
__global__ void f2h_kernel(const float2* __restrict__ in, unsigned* __restrict__ out, int n2)
{
    int i = blockIdx.x * blockDim.x + threadIdx.x;
    if (i < n2) {
        float2 v = in[i];
        out[i] = pack2h(v.x, v.y);
    }
}

// ---------------------------------------------------------------------------
// fp16-in GEMM + bias (fp32 accumulate, fp32 out). cp.async 2-stage pipeline.
// Block 128x128, BK=32, 256 threads (8 warps, warp tile 64x32), 2 CTAs/SM.
// (R11 version, known good)
// ---------------------------------------------------------------------------
#define GBM 128
#define GBN 128
#define GBK 32
#define ASTRIDE 40      // f16 units per A row (80 B)
#define BSTRIDE 136     // f16 units per B row (272 B)
#define ABYTES (GBM * ASTRIDE * 2)     // 10240
#define BBYTES (GBK * BSTRIDE * 2)     // 8704
#define STAGEB (ABYTES + BBYTES)       // 18944
#define GSMEM  (2 * STAGEB)            // 37888

__global__ void __launch_bounds__(256, 2) gemm_f16cp_kernel(
    const __half* __restrict__ A, const __half* __restrict__ B,
    const float* __restrict__ bias, float* __restrict__ C,
    int M, int N, int K)
{
    extern __shared__ char gsm[];
    const unsigned base = smem_u32(gsm);

    const int tid  = threadIdx.x;
    const int lane = tid & 31;
    const int warp = tid >> 5;
    const int wm   = warp >> 2;      // 0..1
    const int wn   = warp & 3;       // 0..3
    const int m0   = blockIdx.y * GBM;
    const int n0   = blockIdx.x * GBN;

    float d[4][4][4];
    #pragma unroll
    for (int i = 0; i < 4; i++)
        #pragma unroll
        for (int j = 0; j < 4; j++)
            #pragma unroll
            for (int c = 0; c < 4; c++) d[i][j][c] = 0.f;

    const unsigned aOff = (unsigned)(((wm * 64 + (lane & 15)) * ASTRIDE + (lane >> 4) * 8) * 2);
    const unsigned bOff = (unsigned)(((lane & 15) * BSTRIDE + wn * 32 + ((lane >> 4) & 1) * 8) * 2);

    auto issue = [&](int it, int s) {
        int k0 = it * GBK;
        unsigned st = base + s * STAGEB;
        {   int r = tid >> 2, c = tid & 3;
            cp16(st + r * 80 + c * 16, A + (size_t)(m0 + r) * K + k0 + c * 8); }
        {   int ch = tid + 256; int r = ch >> 2, c = ch & 3;
            cp16(st + r * 80 + c * 16, A + (size_t)(m0 + r) * K + k0 + c * 8); }
        {   int r = tid >> 4, c = tid & 15;
            cp16(st + ABYTES + r * 272 + c * 16, B + (size_t)(k0 + r) * N + n0 + c * 8); }
        {   int ch = tid + 256; int r = ch >> 4, c = ch & 15;
            cp16(st + ABYTES + r * 272 + c * 16, B + (size_t)(k0 + r) * N + n0 + c * 8); }
        cp_commit();
    };

    const int iters = K / GBK;
    issue(0, 0);

    for (int it = 0; it < iters; it++) {
        const int s = it & 1;
        if (it + 1 < iters) {
            issue(it + 1, s ^ 1);
            cp_wait<1>();
        } else {
            cp_wait<0>();
        }
        __syncthreads();

        const unsigned aB = base + s * STAGEB + aOff;
        const unsigned bB = base + s * STAGEB + ABYTES + bOff;

        #pragma unroll
        for (int kc = 0; kc < GBK; kc += 16) {
            unsigned ah[4][4], bh[2][4];
            #pragma unroll
            for (int tm = 0; tm < 4; tm++)
                ldsm_x4(ah[tm], aB + tm * (16 * ASTRIDE * 2) + kc * 2);
            #pragma unroll
            for (int t2 = 0; t2 < 2; t2++)
                ldsm_x4t(bh[t2], bB + kc * (BSTRIDE * 2) + t2 * 32);
            #pragma unroll
            for (int tm = 0; tm < 4; tm++)
                #pragma unroll
                for (int tn = 0; tn < 4; tn++)
                    mma16816h(d[tm][tn], ah[tm], bh[tn >> 1] + (tn & 1) * 2);
        }
        __syncthreads();
    }

    const int g = lane >> 2, t4 = lane & 3;
    #pragma unroll
    for (int tn = 0; tn < 4; tn++) {
        int col = n0 + wn * 32 + tn * 8 + t4 * 2;
        float bx = bias[col], by = bias[col + 1];
        #pragma unroll
        for (int tm = 0; tm < 4; tm++) {
            int row0 = m0 + wm * 64 + tm * 16 + g;
            *(float2*)(C + (size_t)row0 * N + col) =
                make_float2(d[tm][tn][0] + bx, d[tm][tn][1] + by);
            *(float2*)(C + (size_t)(row0 + 8) * N + col) =
                make_float2(d[tm][tn][2] + bx, d[tm][tn][3] + by);
        }
    }
}

// ---------------------------------------------------------------------------
// Flash attention (causal): QK = 3-term bf16 (accurate logits), PV = 1-term
// fp16 (P in [0,1], fp16 11-bit mantissa; error ~3e-4, within budget).
// 128 queries x 64-key tiles, 8 warps. fp16 att output. Heavy blocks first.
// ---------------------------------------------------------------------------
#define FQ 128
#define FK 64
#define QSTR 136          // 16-bit units per row
#define QSTRU 68          // uint units per row

#define OFF_QH 0
#define OFF_QL (128 * QSTRU)
#define OFF_KH (OFF_QL + 128 * QSTRU)
#define OFF_KL (OFF_KH + 64 * QSTRU)
#define OFF_VH (OFF_KL + 64 * QSTRU)
#define FLASH_SMEM ((OFF_VH + 64 * QSTRU) * 4)   // 121856 bytes

__global__ void __launch_bounds__(256, 1) flash_mma_kernel(
    const float* __restrict__ qkv, unsigned* __restrict__ att)
{
    extern __shared__ unsigned fsm[];
    const unsigned base = smem_u32(fsm);

    const int tid  = threadIdx.x;
    const int lane = tid & 31;
    const int wm   = tid >> 5;          // 0..7 : 16 query rows each
    const int g    = lane >> 2;
    const int t4   = lane & 3;

    const int qi = (int)gridDim.x - 1 - (int)blockIdx.x;   // heavy blocks first
    const int h  = blockIdx.y;
    const int b  = blockIdx.z;
    const int q0 = qi * FQ;
    const float scale_q = 0.08838834764831844f;  // 1/sqrt(128)

    const float* qb = qkv + (size_t)b * TSEQ * 3 * CDIM + h * HD;
    const float* kb = qb + CDIM;
    const float* vb = qb + 2 * CDIM;

    // ---- load + split Q tile (128 x 128), pre-scaled ----
    #pragma unroll
    for (int l = 0; l < 16; l++) {
        int lin = tid + l * 256;
        int r   = lin >> 5;
        int c   = lin & 31;
        float4 v = *(const float4*)(qb + (size_t)(q0 + r) * 3 * CDIM + c * 4);
        unsigned h0, l0, h1, l1;
        split2(v.x * scale_q, v.y * scale_q, h0, l0);
        split2(v.z * scale_q, v.w * scale_q, h1, l1);
        int ui = r * QSTRU + c * 2;
        fsm[OFF_QH + ui] = h0; fsm[OFF_QH + ui + 1] = h1;
        fsm[OFF_QL + ui] = l0; fsm[OFF_QL + ui + 1] = l1;
    }
    __syncthreads();

    unsigned qh[8][4];
    const unsigned aoff = (unsigned)(((wm * 16 + (lane & 15)) * QSTR + (lane >> 4) * 8) * 2);
    #pragma unroll
    for (int ks = 0; ks < 8; ks++)
        ldsm_x4(qh[ks], base + OFF_QH * 4 + aoff + ks * 32);

    float m0r = -INFINITY, m1r = -INFINITY, l0r = 0.f, l1r = 0.f;
    float O[16][4];
    #pragma unroll
    for (int dt = 0; dt < 16; dt++)
        #pragma unroll
        for (int c = 0; c < 4; c++) O[dt][c] = 0.f;

    // x4 K fragment base: pairs of n-tiles per load
    const unsigned k4Off = (unsigned)(
        (((lane & 7) + ((lane >> 4) & 1) * 8) * QSTR + ((lane >> 3) & 1) * 8) * 2);
    // x4t V fragment base: pairs of d-tiles per load
    const unsigned v4Off = (unsigned)(
        ((lane & 15) * QSTR + ((lane >> 4) & 1) * 8) * 2);

    const int jmax = 2 * qi + 2;
    for (int j = 0; j < jmax; j++) {
        __syncthreads();
        // ---- load K (split bf16 hi/lo) + V (fp16) tile (64 x 128) ----
        #pragma unroll
        for (int l = 0; l < 8; l++) {
            int lin = tid + l * 256;
            int r   = lin >> 5;
            int c   = lin & 31;
            size_t goff = (size_t)(j * FK + r) * 3 * CDIM + c * 4;
            int ui = r * QSTRU + c * 2;
            float4 kv = *(const float4*)(kb + goff);
            unsigned h0, lo0, h1, lo1;
            split2(kv.x, kv.y, h0, lo0);
            split2(kv.z, kv.w, h1, lo1);
            fsm[OFF_KH + ui] = h0; fsm[OFF_KH + ui + 1] = h1;
            fsm[OFF_KL + ui] = lo0; fsm[OFF_KL + ui + 1] = lo1;
            float4 vv = *(const float4*)(vb + goff);
            fsm[OFF_VH + ui]     = pack2h(vv.x, vv.y);
            fsm[OFF_VH + ui + 1] = pack2h(vv.z, vv.w);
        }
        __syncthreads();

        // ---- S = Q K^T (3-term bf16) ----
        float S[8][4];
        #pragma unroll
        for (int nt = 0; nt < 8; nt++)
            #pragma unroll
            for (int c = 0; c < 4; c++) S[nt][c] = 0.f;

        #pragma unroll
        for (int ks = 0; ks < 8; ks++) {
            unsigned ql_[4];
            ldsm_x4(ql_, base + OFF_QL * 4 + aoff + ks * 32);
            #pragma unroll
            for (int nt = 0; nt < 8; nt += 2) {
                unsigned koff = k4Off + (unsigned)((nt * 8 * QSTR + ks * 16) * 2);
                unsigned kh4[4], kl4[4];
                ldsm_x4(kh4, base + OFF_KH * 4 + koff);
                ldsm_x4(kl4, base + OFF_KL * 4 + koff);
                mma16816(S[nt],     qh[ks], kh4);
                mma16816(S[nt],     qh[ks], kl4);
                mma16816(S[nt],     ql_,    kh4);
                mma16816(S[nt + 1], qh[ks], kh4 + 2);
                mma16816(S[nt + 1], qh[ks], kl4 + 2);
                mma16816(S[nt + 1], ql_,    kh4 + 2);
            }
        }

        // ---- causal mask (near-diagonal tiles only) ----
        const int rg0 = q0 + wm * 16 + g;
        const int rg1 = rg0 + 8;
        if (j * FK + FK - 1 > q0 + wm * 16) {
            #pragma unroll
            for (int nt = 0; nt < 8; nt++) {
                int kg = j * FK + nt * 8 + 2 * t4;
                if (kg     > rg0) S[nt][0] = -INFINITY;
                if (kg + 1 > rg0) S[nt][1] = -INFINITY;
                if (kg     > rg1) S[nt][2] = -INFINITY;
                if (kg + 1 > rg1) S[nt][3] = -INFINITY;
            }
        }

        // ---- online softmax ----
        float mx0 = -INFINITY, mx1 = -INFINITY;
        #pragma unroll
        for (int nt = 0; nt < 8; nt++) {
            mx0 = fmaxf(mx0, fmaxf(S[nt][0], S[nt][1]));
            mx1 = fmaxf(mx1, fmaxf(S[nt][2], S[nt][3]));
        }
        mx0 = fmaxf(mx0, __shfl_xor_sync(0xffffffffu, mx0, 1));
        mx0 = fmaxf(mx0, __shfl_xor_sync(0xffffffffu, mx0, 2));
        mx1 = fmaxf(mx1, __shfl_xor_sync(0xffffffffu, mx1, 1));
        mx1 = fmaxf(mx1, __shfl_xor_sync(0xffffffffu, mx1, 2));
        float mn0 = fmaxf(m0r, mx0), mn1 = fmaxf(m1r, mx1);
        float sc0 = __expf(m0r - mn0), sc1 = __expf(m1r - mn1);
        m0r = mn0; m1r = mn1;

        float sum0 = 0.f, sum1 = 0.f;
        unsigned ph[16];
        #pragma unroll
        for (int nt = 0; nt < 8; nt++) {
            float p0 = __expf(S[nt][0] - mn0);
            float p1 = __expf(S[nt][1] - mn0);
            float p2 = __expf(S[nt][2] - mn1);
            float p3 = __expf(S[nt][3] - mn1);
            sum0 += p0 + p1; sum1 += p2 + p3;
            ph[2 * nt]     = pack2h(p0, p1);
            ph[2 * nt + 1] = pack2h(p2, p3);
        }
        sum0 += __shfl_xor_sync(0xffffffffu, sum0, 1);
        sum0 += __shfl_xor_sync(0xffffffffu, sum0, 2);
        sum1 += __shfl_xor_sync(0xffffffffu, sum1, 1);
        sum1 += __shfl_xor_sync(0xffffffffu, sum1, 2);
        l0r = l0r * sc0 + sum0;
        l1r = l1r * sc1 + sum1;

        #pragma unroll
        for (int dt = 0; dt < 16; dt++) {
            O[dt][0] *= sc0; O[dt][1] *= sc0;
            O[dt][2] *= sc1; O[dt][3] *= sc1;
        }

        // ---- O += P V  (1-term fp16) ----
        #pragma unroll
        for (int ks = 0; ks < 4; ks++) {
            unsigned pa[4] = {ph[4 * ks], ph[4 * ks + 1], ph[4 * ks + 2], ph[4 * ks + 3]};
            #pragma unroll
            for (int dt = 0; dt < 16; dt += 2) {
                unsigned voff = v4Off + (unsigned)((ks * 16 * QSTR + dt * 8) * 2);
                unsigned vh4[4];
                ldsm_x4t(vh4, base + OFF_VH * 4 + voff);
                mma16816h(O[dt],     pa, vh4);
                mma16816h(O[dt + 1], pa, vh4 + 2);
            }
        }
    }

    // ---- epilogue: normalize + fp16 store ----
    float inv0 = 1.f / l0r, inv1 = 1.f / l1r;
    const int rg0 = q0 + wm * 16 + g;
    #pragma unroll
    for (int dt = 0; dt < 16; dt++) {
        int col = dt * 8 + 2 * t4;
        size_t idx0 = (((size_t)b * TSEQ + rg0) * CDIM + h * HD + col) >> 1;
        size_t idx1 = (((size_t)b * TSEQ + rg0 + 8) * CDIM + h * HD + col) >> 1;
        att[idx0] = pack2h(O[dt][0] * inv0, O[dt][1] * inv0);
        att[idx1] = pack2h(O[dt][2] * inv1, O[dt][3] * inv1);
    }
}

// ---------------------------------------------------------------------------
extern "C" void kernel_launch(void* const* d_in, const int* in_sizes, int n_in,
                              void* d_out, int out_size)
{
    const float* x      = (const float*)d_in[0];
    const float* w_attn = (const float*)d_in[1];
    const float* b_attn = (const float*)d_in[2];
    const float* w_proj = (const float*)d_in[3];
    const float* b_proj = (const float*)d_in[4];
    float* out = (float*)d_out;

    unsigned *xh, *wah, *wph, *att;
    float *qkv;
    cudaGetSymbolAddress((void**)&xh,  g_xh);
    cudaGetSymbolAddress((void**)&wah, g_wah);
    cudaGetSymbolAddress((void**)&wph, g_wph);
    cudaGetSymbolAddress((void**)&qkv, g_qkv);
    cudaGetSymbolAddress((void**)&att, g_att);

    cudaFuncSetAttribute(gemm_f16cp_kernel,
                         cudaFuncAttributeMaxDynamicSharedMemorySize, GSMEM);
    cudaFuncSetAttribute(flash_mma_kernel,
                         cudaFuncAttributeMaxDynamicSharedMemorySize, FLASH_SMEM);

    const int M = BDIM * TSEQ;  // 4096

    // 0) one-time fp32 -> fp16 conversion
    int n2x = BDIM * TSEQ * CDIM / 2;
    int n2a = CDIM * 3 * CDIM / 2;
    int n2p = CDIM * CDIM / 2;
    f2h_kernel<<<(n2x + 255) / 256, 256>>>((const float2*)x,      xh,  n2x);
    f2h_kernel<<<(n2a + 255) / 256, 256>>>((const float2*)w_attn, wah, n2a);
    f2h_kernel<<<(n2p + 255) / 256, 256>>>((const float2*)w_proj, wph, n2p);

    // 1) QKV = x @ w_attn + b_attn    (fp16 in, fp32 out)
    gemm_f16cp_kernel<<<dim3(3 * CDIM / GBN, M / GBM), 256, GSMEM>>>(
        (const __half*)xh, (const __half*)wah, b_attn, qkv, M, 3 * CDIM, CDIM);

    // 2) Flash attention (QK bf16 3-term, PV fp16 1-term) -> fp16 att
    flash_mma_kernel<<<dim3(TSEQ / FQ, NHEAD, BDIM), 256, FLASH_SMEM>>>(qkv, att);

    // 3) out = att @ w_proj + b_proj  (fp16 in, fp32 out)
    gemm_f16cp_kernel<<<dim3(CDIM / GBN, M / GBM), 256, GSMEM>>>(
        (const __half*)att, (const __half*)wph, b_proj, out, M, CDIM, CDIM);
}